// round 9
// baseline (speedup 1.0000x reference)
#include <cuda_runtime.h>
#include <math.h>
#include <cstdint>

#define BT   128     // threads per block (2 warps per 32-point group)
#define PT   64      // points per block
#define NCH  101     // 100 SH channels + 1 time index
#define LMAX 10

// ---------------- compile-time normalization constants ----------------
__host__ __device__ constexpr double csqrt_(double x) {
    double g = (x > 1.0) ? x : 1.0;
    for (int i = 0; i < 64; i++) g = 0.5 * (g + x / g);
    return g;
}
__host__ __device__ constexpr double Kd(int l, int am) {
    double ratio = 1.0;                       // (l-am)! / (l+am)!
    for (int k = l - am + 1; k <= l + am; k++) ratio /= (double)k;
    double v = csqrt_((double)(2 * l + 1) * 0.07957747154594767 * ratio);
    if (am > 0) v *= csqrt_(2.0);             // fold sqrt(2) for |m|>0
    return v;
}

// Store Y_L^{±M} given P_L^M value and cos/sin(M*phi); K folded at compile time.
template <int L, int M>
__device__ __forceinline__ void store_lm(float p, float cm, float sm,
                                         float* __restrict__ st) {
    constexpr float Kc = (float)Kd(L, M);
    if constexpr (M == 0) {
        st[L * L + L] = Kc * p;
    } else {
        st[L * L + L + M] = Kc * cm * p;
        st[L * L + L - M] = Kc * sm * p;
    }
}

// Remaining Legendre recurrence steps l = L..LMAX-1 for order M.
template <int M, int L>
__device__ __forceinline__ void leg_rest(float x, float plm1, float plm2,
                                         float cm, float sm,
                                         float* __restrict__ st) {
    if constexpr (L < LMAX) {
        const float pl = ((float)(2 * L - 1) * x * plm1
                          - (float)(L + M - 1) * plm2) * (1.0f / (float)(L - M));
        store_lm<L, M>(pl, cm, sm, st);
        leg_rest<M, L + 1>(x, pl, plm1, cm, sm, st);
    }
}

// Full chain for order M given seed pmm = P_M^M and cos/sin(M*phi).
template <int M>
__device__ __forceinline__ void chain(float x, float cm, float sm, float pmm,
                                      float* __restrict__ st) {
    store_lm<M, M>(pmm, cm, sm, st);
    if constexpr (M + 1 < LMAX) {
        const float p1 = x * (float)(2 * M + 1) * pmm;
        store_lm<M + 1, M>(p1, cm, sm, st);
        leg_rest<M, M + 2>(x, p1, pmm, cm, sm, st);
    }
}

// Run chains m = M0, M0+2, ... advancing pmm and cos/sin(m*phi) by 2 each step.
template <int M0>
__device__ __forceinline__ void sh_run(float x, float s, float c2, float s2,
                                       float cm, float sm, float pmm,
                                       float* __restrict__ st) {
    chain<M0>(x, cm, sm, pmm, st);
    if constexpr (M0 + 2 < LMAX) {
        const float pn = pmm * (float)((2 * M0 + 1) * (2 * M0 + 3)) * s * s;
        const float cn = cm * c2 - sm * s2;
        const float sn = sm * c2 + cm * s2;
        sh_run<M0 + 2>(x, s, c2, s2, cn, sn, pn, st);
    }
}

__global__ __launch_bounds__(BT) void sh_kernel(const float* __restrict__ lonlat,
                                                float* __restrict__ out,
                                                int N) {
    __shared__ __align__(16) float stage[PT * NCH];

    const int tid  = threadIdx.x;
    const int wid  = tid >> 5;
    const int lane = tid & 31;

    // warp pair layout: warps {0,1} -> points 0..31, warps {2,3} -> points 32..63
    const int p    = lane + (wid >> 1) * 32;     // point within block
    const int half = wid & 1;                    // 0: even m, 1: odd m
    const long long i = (long long)blockIdx.x * PT + p;

    if (i < N) {
        const float lon = lonlat[i * 3 + 0];
        const float lat = lonlat[i * 3 + 1];

        const float D2R = 0.017453292519943295f;
        const float phi = (lon + 180.0f) * D2R;
        const float th  = (lat +  90.0f) * D2R;

        float s, x;                  // sin(theta), cos(theta)
        sincosf(th, &s, &x);
        float s1, c1;                // sin(phi), cos(phi)
        sincosf(phi, &s1, &c1);

        const float c2 = c1 * c1 - s1 * s1;
        const float s2 = 2.0f * c1 * s1;

        float* st = &stage[p * NCH];
        if (half == 0) {
            sh_run<0>(x, s, c2, s2, 1.0f, 0.0f, 1.0f, st);
            st[100] = lonlat[i * 3 + 2];         // time index
        } else {
            sh_run<1>(x, s, c2, s2, c1, s1, -s, st);
        }
    }
    __syncthreads();

    // ---- TMA bulk store: flush the whole 25,856 B tile smem -> gmem ----
    const long long blockBase = (long long)blockIdx.x * PT;
    long long rem = (long long)N - blockBase;
    const int nvalid = (rem >= PT) ? PT : (rem > 0 ? (int)rem : 0);

    if (nvalid == PT) {
        // order the generic-proxy STS writes before the async-proxy TMA read
        asm volatile("fence.proxy.async.shared::cta;" ::: "memory");
        if (tid == 0) {
            uint32_t s_addr;
            asm("{ .reg .u64 t; cvta.to.shared.u64 t, %1; cvt.u32.u64 %0, t; }"
                : "=r"(s_addr) : "l"(stage));
            uint64_t g_addr = (uint64_t)(uintptr_t)(out + blockBase * NCH);
            asm volatile(
                "cp.async.bulk.global.shared::cta.bulk_group [%0], [%1], %2;"
                :: "l"(g_addr), "r"(s_addr), "r"((int)(PT * NCH * 4))
                : "memory");
            asm volatile("cp.async.bulk.commit_group;" ::: "memory");
            asm volatile("cp.async.bulk.wait_group 0;" ::: "memory");
        }
    } else if (nvalid > 0) {
        const int tot = nvalid * NCH;
        float* o = out + blockBase * NCH;
        for (int j = tid; j < tot; j += BT) {
            __stcs(&o[j], stage[j]);
        }
    }
}

extern "C" void kernel_launch(void* const* d_in, const int* in_sizes, int n_in,
                              void* d_out, int out_size) {
    const float* lonlat = (const float*)d_in[0];
    const int N = in_sizes[0] / 3;
    float* out = (float*)d_out;
    const int nb = (N + PT - 1) / PT;
    sh_kernel<<<nb, BT>>>(lonlat, out, N);
}

// round 10
// speedup vs baseline: 1.0031x; 1.0031x over previous
#include <cuda_runtime.h>
#include <math.h>
#include <cstdint>

#define BT   128     // threads per block (2 warps per 32-point group)
#define PT   64      // points per block
#define NCH  101     // 100 SH channels + 1 time index
#define LMAX 10

// ---------------- compile-time normalization constants ----------------
__host__ __device__ constexpr double csqrt_(double x) {
    double g = (x > 1.0) ? x : 1.0;
    for (int i = 0; i < 64; i++) g = 0.5 * (g + x / g);
    return g;
}
__host__ __device__ constexpr double Kd(int l, int am) {
    double ratio = 1.0;                       // (l-am)! / (l+am)!
    for (int k = l - am + 1; k <= l + am; k++) ratio /= (double)k;
    double v = csqrt_((double)(2 * l + 1) * 0.07957747154594767 * ratio);
    if (am > 0) v *= csqrt_(2.0);             // fold sqrt(2) for |m|>0
    return v;
}

// Store Y_L^{±M} given P_L^M value and cos/sin(M*phi); K folded at compile time.
template <int L, int M>
__device__ __forceinline__ void store_lm(float p, float cm, float sm,
                                         float* __restrict__ st) {
    constexpr float Kc = (float)Kd(L, M);
    if constexpr (M == 0) {
        st[L * L + L] = Kc * p;
    } else {
        st[L * L + L + M] = Kc * cm * p;
        st[L * L + L - M] = Kc * sm * p;
    }
}

// Remaining Legendre recurrence steps l = L..LMAX-1 for order M.
template <int M, int L>
__device__ __forceinline__ void leg_rest(float x, float plm1, float plm2,
                                         float cm, float sm,
                                         float* __restrict__ st) {
    if constexpr (L < LMAX) {
        const float pl = ((float)(2 * L - 1) * x * plm1
                          - (float)(L + M - 1) * plm2) * (1.0f / (float)(L - M));
        store_lm<L, M>(pl, cm, sm, st);
        leg_rest<M, L + 1>(x, pl, plm1, cm, sm, st);
    }
}

// Full chain for order M given seed pmm = P_M^M and cos/sin(M*phi).
template <int M>
__device__ __forceinline__ void chain(float x, float cm, float sm, float pmm,
                                      float* __restrict__ st) {
    store_lm<M, M>(pmm, cm, sm, st);
    if constexpr (M + 1 < LMAX) {
        const float p1 = x * (float)(2 * M + 1) * pmm;
        store_lm<M + 1, M>(p1, cm, sm, st);
        leg_rest<M, M + 2>(x, p1, pmm, cm, sm, st);
    }
}

// Run chains m = M0, M0+2, ... advancing pmm and cos/sin(m*phi) by 2 each step.
template <int M0>
__device__ __forceinline__ void sh_run(float x, float s, float c2, float s2,
                                       float cm, float sm, float pmm,
                                       float* __restrict__ st) {
    chain<M0>(x, cm, sm, pmm, st);
    if constexpr (M0 + 2 < LMAX) {
        const float pn = pmm * (float)((2 * M0 + 1) * (2 * M0 + 3)) * s * s;
        const float cn = cm * c2 - sm * s2;
        const float sn = sm * c2 + cm * s2;
        sh_run<M0 + 2>(x, s, c2, s2, cn, sn, pn, st);
    }
}

__global__ __launch_bounds__(BT) void sh_kernel(const float* __restrict__ lonlat,
                                                float* __restrict__ out,
                                                int N) {
    __shared__ __align__(32) float stage[PT * NCH];

    const int tid  = threadIdx.x;
    const int wid  = tid >> 5;
    const int lane = tid & 31;

    // warp pair layout: warps {0,1} -> points 0..31, warps {2,3} -> points 32..63
    const int p    = lane + (wid >> 1) * 32;     // point within block
    const int half = wid & 1;                    // 0: even m, 1: odd m
    const long long i = (long long)blockIdx.x * PT + p;

    if (i < N) {
        const float lon = lonlat[i * 3 + 0];
        const float lat = lonlat[i * 3 + 1];

        const float D2R = 0.017453292519943295f;
        const float phi = (lon + 180.0f) * D2R;
        const float th  = (lat +  90.0f) * D2R;

        float s, x;                  // sin(theta), cos(theta)
        sincosf(th, &s, &x);
        float s1, c1;                // sin(phi), cos(phi)
        sincosf(phi, &s1, &c1);

        const float c2 = c1 * c1 - s1 * s1;
        const float s2 = 2.0f * c1 * s1;

        float* st = &stage[p * NCH];
        if (half == 0) {
            sh_run<0>(x, s, c2, s2, 1.0f, 0.0f, 1.0f, st);
            st[100] = lonlat[i * 3 + 2];         // time index
        } else {
            sh_run<1>(x, s, c2, s2, c1, s1, -s, st);
        }
    }
    __syncthreads();

    // ---- coalesced streaming copy-out, 256-bit stores (STG.256) ----
    const long long blockBase = (long long)blockIdx.x * PT;
    long long rem = (long long)N - blockBase;
    const int nvalid = (rem >= PT) ? PT : (rem > 0 ? (int)rem : 0);

    if (nvalid == PT) {
        const float4* s4 = (const float4*)stage;
        float* obase = out + blockBase * NCH;
        constexpr int NCHUNK = (PT * NCH * 4) / 32;      // 808 x 32B chunks
        #pragma unroll 4
        for (int j = tid; j < NCHUNK; j += BT) {
            const float4 a = s4[2 * j];
            const float4 b = s4[2 * j + 1];
            asm volatile(
                "st.global.cs.v8.f32 [%0], {%1,%2,%3,%4,%5,%6,%7,%8};"
                :: "l"(obase + (size_t)j * 8),
                   "f"(a.x), "f"(a.y), "f"(a.z), "f"(a.w),
                   "f"(b.x), "f"(b.y), "f"(b.z), "f"(b.w)
                : "memory");
        }
    } else if (nvalid > 0) {
        const int tot = nvalid * NCH;
        float* o = out + blockBase * NCH;
        for (int j = tid; j < tot; j += BT) {
            __stcs(&o[j], stage[j]);
        }
    }
}

extern "C" void kernel_launch(void* const* d_in, const int* in_sizes, int n_in,
                              void* d_out, int out_size) {
    const float* lonlat = (const float*)d_in[0];
    const int N = in_sizes[0] / 3;
    float* out = (float*)d_out;
    const int nb = (N + PT - 1) / PT;
    sh_kernel<<<nb, BT>>>(lonlat, out, N);
}

// round 14
// speedup vs baseline: 1.0710x; 1.0676x over previous
#include <cuda_runtime.h>
#include <math.h>

#define BT   128     // threads per block (2 warps per 32-point group)
#define PT   64      // points per block
#define NCH  101     // 100 SH channels + 1 time index
#define LMAX 10

// ---------------- compile-time normalization constants ----------------
__host__ __device__ constexpr double csqrt_(double x) {
    double g = (x > 1.0) ? x : 1.0;
    for (int i = 0; i < 64; i++) g = 0.5 * (g + x / g);
    return g;
}
__host__ __device__ constexpr double Kd(int l, int am) {
    double ratio = 1.0;                       // (l-am)! / (l+am)!
    for (int k = l - am + 1; k <= l + am; k++) ratio /= (double)k;
    double v = csqrt_((double)(2 * l + 1) * 0.07957747154594767 * ratio);
    if (am > 0) v *= csqrt_(2.0);             // fold sqrt(2) for |m|>0
    return v;
}

// Store Y_L^{±M} given P_L^M value and cos/sin(M*phi); K folded at compile time.
template <int L, int M>
__device__ __forceinline__ void store_lm(float p, float cm, float sm,
                                         float* __restrict__ st) {
    constexpr float Kc = (float)Kd(L, M);
    if constexpr (M == 0) {
        st[L * L + L] = Kc * p;
    } else {
        st[L * L + L + M] = Kc * cm * p;
        st[L * L + L - M] = Kc * sm * p;
    }
}

// Remaining Legendre recurrence steps l = L..LMAX-1 for order M.
template <int M, int L>
__device__ __forceinline__ void leg_rest(float x, float plm1, float plm2,
                                         float cm, float sm,
                                         float* __restrict__ st) {
    if constexpr (L < LMAX) {
        const float pl = ((float)(2 * L - 1) * x * plm1
                          - (float)(L + M - 1) * plm2) * (1.0f / (float)(L - M));
        store_lm<L, M>(pl, cm, sm, st);
        leg_rest<M, L + 1>(x, pl, plm1, cm, sm, st);
    }
}

// Full chain for order M given seed pmm = P_M^M and cos/sin(M*phi).
template <int M>
__device__ __forceinline__ void chain(float x, float cm, float sm, float pmm,
                                      float* __restrict__ st) {
    store_lm<M, M>(pmm, cm, sm, st);
    if constexpr (M + 1 < LMAX) {
        const float p1 = x * (float)(2 * M + 1) * pmm;
        store_lm<M + 1, M>(p1, cm, sm, st);
        leg_rest<M, M + 2>(x, p1, pmm, cm, sm, st);
    }
}

// Run chains m = M0, M0+2, ... advancing pmm and cos/sin(m*phi) by 2 each step.
template <int M0>
__device__ __forceinline__ void sh_run(float x, float s, float c2, float s2,
                                       float cm, float sm, float pmm,
                                       float* __restrict__ st) {
    chain<M0>(x, cm, sm, pmm, st);
    if constexpr (M0 + 2 < LMAX) {
        const float pn = pmm * (float)((2 * M0 + 1) * (2 * M0 + 3)) * s * s;
        const float cn = cm * c2 - sm * s2;
        const float sn = sm * c2 + cm * s2;
        sh_run<M0 + 2>(x, s, c2, s2, cn, sn, pn, st);
    }
}

__global__ __launch_bounds__(BT) void sh_kernel(const float* __restrict__ lonlat,
                                                float* __restrict__ out,
                                                int N) {
    __shared__ __align__(16) float stage[PT * NCH];

    const int tid  = threadIdx.x;
    const int wid  = tid >> 5;
    const int lane = tid & 31;

    // warp pair layout: warps {0,1} -> points 0..31, warps {2,3} -> points 32..63
    const int p    = lane + (wid >> 1) * 32;     // point within block
    const int half = wid & 1;                    // 0: even m, 1: odd m
    const long long i = (long long)blockIdx.x * PT + p;

    if (i < N) {
        const float lon = __ldg(&lonlat[i * 3 + 0]);
        const float lat = __ldg(&lonlat[i * 3 + 1]);

        const float D2R = 0.017453292519943295f;
        const float phi = (lon + 180.0f) * D2R;
        const float th  = (lat +  90.0f) * D2R;

        float s, x;                  // sin(theta), cos(theta)
        sincosf(th, &s, &x);
        float s1, c1;                // sin(phi), cos(phi)
        sincosf(phi, &s1, &c1);

        const float c2 = c1 * c1 - s1 * s1;
        const float s2 = 2.0f * c1 * s1;

        float* st = &stage[p * NCH];
        if (half == 0) {
            sh_run<0>(x, s, c2, s2, 1.0f, 0.0f, 1.0f, st);
            st[100] = __ldg(&lonlat[i * 3 + 2]);     // time index
        } else {
            sh_run<1>(x, s, c2, s2, c1, s1, -s, st);
        }
    }
    __syncthreads();

    // ---- coalesced streaming copy-out of the block tile ----
    const long long blockBase = (long long)blockIdx.x * PT;
    long long rem = (long long)N - blockBase;
    const int nvalid = (rem >= PT) ? PT : (rem > 0 ? (int)rem : 0);

    if (nvalid == PT) {
        const float4* s4 = (const float4*)stage;
        float4* o4 = (float4*)(out + blockBase * NCH);
        #pragma unroll 4
        for (int j = tid; j < (PT * NCH) / 4; j += BT) {
            __stcs(&o4[j], s4[j]);
        }
    } else if (nvalid > 0) {
        const int tot = nvalid * NCH;
        float* o = out + blockBase * NCH;
        for (int j = tid; j < tot; j += BT) {
            __stcs(&o[j], stage[j]);
        }
    }
}

extern "C" void kernel_launch(void* const* d_in, const int* in_sizes, int n_in,
                              void* d_out, int out_size) {
    const float* lonlat = (const float*)d_in[0];
    const int N = in_sizes[0] / 3;
    float* out = (float*)d_out;
    const int nb = (N + PT - 1) / PT;
    sh_kernel<<<nb, BT>>>(lonlat, out, N);
}